// round 10
// baseline (speedup 1.0000x reference)
#include <cuda_runtime.h>
#include <cuda_bf16.h>
#include <cstdint>

// ===================== constants =====================
#define NTOK   16384
#define DIM    512
#define INV_T  14.285714285714286f   // 1/0.07
#define MARGIN 0.1f
#define QS     384.0f                // int8 quantization scale
#define INV_TS (14.285714285714286f / (384.0f * 384.0f))

#define GRIDX   2048                 // CTAs; each does 8 row-tiles, fixed col-tile
#define NTILES  16384
#define NCH     4                    // K chunks: 512 int8 / 128 per chunk
#define B_BYTES (NCH * 16384)        // resident B: 4 chunks x 16KB = 64KB
#define A_STAGE 16384                // one A stage (128 rows x 128B)
#define SMEM_SZ (B_BYTES + 2 * A_STAGE + 1024)

typedef unsigned long long u64;

// ===================== device globals (no cudaMalloc allowed) =====================
__device__ signed char g_sn[(size_t)NTOK * DIM];   // int8, scaled by QS
__device__ signed char g_tn[(size_t)NTOK * DIM];
__device__ float g_diag[NTOK];                     // exact fp32 diagonal cos-sims
__device__ double g_sum;

// ===================== helpers =====================
__device__ __forceinline__ uint32_t smem_u32(const void* p) {
    uint32_t a;
    asm("{ .reg .u64 t; cvta.to.shared.u64 t, %1; cvt.u32.u64 %0, t; }" : "=r"(a) : "l"(p));
    return a;
}
__device__ __forceinline__ void cp_async16(uint32_t smem, const void* gmem) {
    asm volatile("cp.async.cg.shared.global [%0], [%1], 16;" :: "r"(smem), "l"(gmem));
}
#define CP_COMMIT() asm volatile("cp.async.commit_group;" ::: "memory")
#define CP_WAIT(n)  asm volatile("cp.async.wait_group %0;" :: "n"(n) : "memory")

__device__ __forceinline__ void ldsm4(uint32_t* r, uint32_t addr) {
    asm volatile("ldmatrix.sync.aligned.m8n8.x4.shared.b16 {%0,%1,%2,%3}, [%4];"
                 : "=r"(r[0]), "=r"(r[1]), "=r"(r[2]), "=r"(r[3]) : "r"(addr));
}
// int8 IMMA: 4096 MACs/instruction, fragments byte-identical to bf16 m16n8k16 path
__device__ __forceinline__ void mma16832i(int* c, const uint32_t* a, uint32_t b0, uint32_t b1) {
    asm volatile(
        "mma.sync.aligned.m16n8k32.row.col.s32.s8.s8.s32 "
        "{%0,%1,%2,%3}, {%4,%5,%6,%7}, {%8,%9}, {%0,%1,%2,%3};"
        : "+r"(c[0]), "+r"(c[1]), "+r"(c[2]), "+r"(c[3])
        : "r"(a[0]), "r"(a[1]), "r"(a[2]), "r"(a[3]), "r"(b0), "r"(b1));
}
#define SWZ(off) ((off) ^ (((off) >> 3) & 0x70))

// ===================== packed f32x2 helpers =====================
__device__ __forceinline__ u64 pfma(u64 a, u64 b, u64 c) {
    u64 d; asm("fma.rn.f32x2 %0, %1, %2, %3;" : "=l"(d) : "l"(a), "l"(b), "l"(c)); return d;
}
__device__ __forceinline__ u64 pmul(u64 a, u64 b) {
    u64 d; asm("mul.rn.f32x2 %0, %1, %2;" : "=l"(d) : "l"(a), "l"(b)); return d;
}
__device__ __forceinline__ u64 padd(u64 a, u64 b) {
    u64 d; asm("add.rn.f32x2 %0, %1, %2;" : "=l"(d) : "l"(a), "l"(b)); return d;
}
__device__ __forceinline__ u64 pack2(float lo, float hi) {
    u64 d; asm("mov.b64 %0, {%1, %2};" : "=l"(d) : "f"(lo), "f"(hi)); return d;
}
__device__ __forceinline__ void unpack2(uint32_t& lo, uint32_t& hi, u64 x) {
    asm("mov.b64 {%0, %1}, %2;" : "=r"(lo), "=r"(hi) : "l"(x));
}
__device__ __forceinline__ u64 bcast(float v) {
    uint32_t b = __float_as_uint(v);
    return ((u64)b << 32) | b;
}

// ===================== scalar softplus (accurate; finalize only) =====================
__device__ __forceinline__ float softplus_fast(float x) {
    float ax = fminf(fabsf(x), 20.0f);
    float r  = fmaxf(x, 0.0f);
    float t  = ax * -1.4426950408889634f;
    float kf = t + 12582912.0f;
    int   sc = __float_as_int(kf) << 23;
    float f  = t - (kf - 12582912.0f);
    float p  = 1.3333558146e-3f;
    p = fmaf(p, f, 9.6181291918e-3f);
    p = fmaf(p, f, 5.5504108664e-2f);
    p = fmaf(p, f, 2.4022650696e-1f);
    p = fmaf(p, f, 6.9314718056e-1f);
    p = fmaf(p, f, 1.0f);
    float e = __int_as_float(__float_as_int(p) + sc);
    float d = e + 2.0f;
    float y = fmaf(d, -0.16666667f, 0.83333333f);
    y = y * fmaf(-d, y, 2.0f);
    y = y * fmaf(-d, y, 2.0f);
    float z  = e * y;
    float z2 = z * z;
    float q  = 0.22222222f;
    q = fmaf(q, z2, 0.28571429f);
    q = fmaf(q, z2, 0.4f);
    q = fmaf(q, z2, 0.66666667f);
    q = fmaf(q, z2, 2.0f);
    return fmaf(z, q, r);
}

// ===================== kernel 1: L2-normalize rows + diag dot, fp32 -> int8*QS ============
__global__ __launch_bounds__(256) void normalize_kernel(const float* __restrict__ S,
                                                        const float* __restrict__ T) {
    int row = blockIdx.x;
    int tid = threadIdx.x;
    if (row == 0 && tid == 0) g_sum = 0.0;

    const float2* s2 = (const float2*)(S + (size_t)row * DIM);
    const float2* t2 = (const float2*)(T + (size_t)row * DIM);
    float2 sv = s2[tid];
    float2 tv = t2[tid];
    float a = fmaf(sv.x, sv.x, sv.y * sv.y);
    float b = fmaf(tv.x, tv.x, tv.y * tv.y);
    float c = fmaf(sv.x, tv.x, sv.y * tv.y);
    #pragma unroll
    for (int o = 16; o; o >>= 1) {
        a += __shfl_xor_sync(0xffffffffu, a, o);
        b += __shfl_xor_sync(0xffffffffu, b, o);
        c += __shfl_xor_sync(0xffffffffu, c, o);
    }
    __shared__ float sa[8], sb[8], sc[8];
    int w = tid >> 5, l = tid & 31;
    if (l == 0) { sa[w] = a; sb[w] = b; sc[w] = c; }
    __syncthreads();
    float ta = 0.f, tb = 0.f, tc = 0.f;
    #pragma unroll
    for (int i = 0; i < 8; i++) { ta += sa[i]; tb += sb[i]; tc += sc[i]; }
    float ia = rsqrtf(ta);
    float ib = rsqrtf(tb);
    if (tid == 0) g_diag[row] = tc * ia * ib;
    float qa = ia * QS, qb = ib * QS;

    int sx = __float2int_rn(fminf(fmaxf(sv.x * qa, -127.f), 127.f));
    int sy = __float2int_rn(fminf(fmaxf(sv.y * qa, -127.f), 127.f));
    int tx = __float2int_rn(fminf(fmaxf(tv.x * qb, -127.f), 127.f));
    int ty = __float2int_rn(fminf(fmaxf(tv.y * qb, -127.f), 127.f));
    unsigned short so = (unsigned short)((sx & 0xFF) | ((sy & 0xFF) << 8));
    unsigned short to = (unsigned short)((tx & 0xFF) | ((ty & 0xFF) << 8));
    ((unsigned short*)g_sn)[(size_t)row * (DIM / 2) + tid] = so;
    ((unsigned short*)g_tn)[(size_t)row * (DIM / 2) + tid] = to;
}

// ===================== packed softplus pair (int inputs), accumulated into eL/eS ==========
// reciprocal: chord seed (5/6 - d/6) + TWO Newton steps — R5/R9-validated.
#define EPI_PAIR(I0, I1) do { \
    u64 _pa = pack2((float)(I0), (float)(I1)); \
    u64 _x  = pfma(_pa, c_invT, c_negM); \
    u64 _ax = _x & 0x7FFFFFFF7FFFFFFFull; \
    u64 _t  = pmul(_ax, c_negL2E); \
    u64 _kf = padd(_t, c_magic); \
    u64 _f  = pfma(padd(_kf, c_nmagic), c_neg1, _t); \
    u64 _p  = pfma(c_e4, _f, c_e3); \
    _p = pfma(_p, _f, c_e2); \
    _p = pfma(_p, _f, c_e1); \
    _p = pfma(_p, _f, c_one); \
    uint32_t _klo, _khi, _plo, _phi; \
    unpack2(_klo, _khi, _kf); \
    unpack2(_plo, _phi, _p); \
    _plo += _klo << 23; \
    _phi += _khi << 23; \
    u64 _e; asm("mov.b64 %0, {%1, %2};" : "=l"(_e) : "r"(_plo), "r"(_phi)); \
    u64 _nd = pfma(_e, c_neg1, c_neg2); \
    u64 _y  = pfma(_nd, c_16, c_56); \
    _y = pmul(_y, pfma(_nd, _y, c_two)); \
    _y = pmul(_y, pfma(_nd, _y, c_two)); \
    u64 _z  = pmul(_e, _y); \
    u64 _z2 = pmul(_z, _z); \
    u64 _q  = pfma(c_q3, _z2, c_q2); \
    _q = pfma(_q, _z2, c_q1); \
    _q = pfma(_q, _z2, c_two); \
    eL = pfma(_z, _q, eL); \
    eS = padd(eS, _x); \
    eS = padd(eS, _ax); \
} while (0)

// mainloop over one 128x128 tile into ACC (int32), epilogue of PREV interleaved (2 pairs/ks)
#define DO_TILE(ACC, PREV) do { \
    _Pragma("unroll") \
    for (int _i = 0; _i < 64; ++_i) ACC[_i] = 0; \
    _Pragma("unroll") \
    for (int c = 0; c < NCH; ++c) { \
        CP_WAIT(1); \
        __syncthreads(); \
        uint32_t aBase = sA + (uint32_t)(c & 1) * A_STAGE; \
        uint32_t bBase = sB + (uint32_t)c * A_STAGE; \
        _Pragma("unroll") \
        for (int ks = 0; ks < 4; ++ks) { \
            uint32_t afr[2][4]; \
            _Pragma("unroll") \
            for (int mi = 0; mi < 2; ++mi) { \
                int row = aRow + (mi << 4); \
                uint32_t kb = (uint32_t)(aKsel + (ks << 5)); \
                ldsm4(afr[mi], aBase + (row << 7) + (kb ^ ((row & 7) << 4))); \
            } \
            _Pragma("unroll") \
            for (int nb = 0; nb < 4; ++nb) { \
                uint32_t bfr[4]; \
                int row = bRow + (nb << 4); \
                uint32_t kb = (uint32_t)(bKsel + (ks << 5)); \
                ldsm4(bfr, bBase + (row << 7) + (kb ^ ((row & 7) << 4))); \
                _Pragma("unroll") \
                for (int mi = 0; mi < 2; ++mi) { \
                    mma16832i(&ACC[((mi << 3) + (nb << 1)) << 2],     afr[mi], bfr[0], bfr[1]); \
                    mma16832i(&ACC[((mi << 3) + (nb << 1) + 1) << 2], afr[mi], bfr[2], bfr[3]); \
                } \
            } \
            { int _p0 = ((c << 2) + ks) << 1; \
              EPI_PAIR(PREV[_p0 * 2],     PREV[_p0 * 2 + 1]); \
              EPI_PAIR(PREV[_p0 * 2 + 2], PREV[_p0 * 2 + 3]); } \
        } \
        __syncthreads(); \
        { \
            const uint8_t* psrc = (c < 2) ? gAc : gAn; \
            uint32_t pch = (c < 2) ? (uint32_t)(c + 2) : (uint32_t)(c - 2); \
            uint32_t pst = sA + (uint32_t)(c & 1) * A_STAGE; \
            _Pragma("unroll") \
            for (int _i = 0; _i < 4; ++_i) cp_async16(pst + soff[_i], psrc + gofs[_i] + pch * 128u); \
            CP_COMMIT(); \
        } \
    } \
    gAc = gAn; \
    t += GRIDX; \
    { int tnn = t + GRIDX; if (tnn >= NTILES) tnn = t; \
      gAn = (const uint8_t*)g_sn + ((size_t)(((tnn >> 10) << 3) + rband) << 16); } \
} while (0)

// ===================== kernel 2: persistent-col int8 GEMM + pipelined softplus epilogue =====
// 256 threads (8 warps, 4x2), warp tile 32x64. B col-tile resident (64KB), A streams.
__global__ __launch_bounds__(256, 1) void gemm_loss_kernel() {
    extern __shared__ uint8_t dynsmem[];
    __shared__ float s_red[8];

    int tid  = threadIdx.x;
    int wid  = tid >> 5;
    int lane = tid & 31;
    int bid  = blockIdx.x;

    uint32_t rbase = smem_u32(dynsmem);
    uint32_t base  = (rbase + 1023u) & ~1023u;
    uint32_t sB = base;                  // 4 resident B chunks
    uint32_t sA = base + B_BYTES;        // 2 A stages

    // this CTA: fixed col-tile bc, row-tiles t = bid + k*GRIDX (8-row bands for L2)
    int rband = bid & 7;
    int bc    = (bid & 1023) >> 3;
    int t     = bid;
    const uint8_t* gAc = (const uint8_t*)g_sn + ((size_t)(((t >> 10) << 3) + rband) << 16);
    const uint8_t* gAn = (const uint8_t*)g_sn + ((size_t)((((t + GRIDX) >> 10) << 3) + rband) << 16);
    const uint8_t* gB  = (const uint8_t*)g_tn + ((size_t)bc << 16);

    // per-thread cp.async slots: 4 x 16B covers one 16KB chunk with 256 threads
    uint32_t soff[4], gofs[4];
    #pragma unroll
    for (int i = 0; i < 4; i++) {
        int idx = tid + (i << 8);
        int r   = idx >> 3, sg = idx & 7;
        soff[i] = SWZ((r << 7) + (sg << 4));
        gofs[i] = r * DIM + (sg << 4);       // int8: row stride = 512 bytes
    }

    // ldmatrix components (validated R4/R9 mapping; byte-identical for int8)
    int wm = wid & 3, wn = wid >> 2;
    int aRow  = (wm << 5) + (lane & 15);
    int aKsel = (lane >> 4) << 4;
    int bRow  = (wn << 6) + (lane & 7) + ((lane & 16) >> 1);
    int bKsel = (lane & 8) << 1;

    // epilogue constants
    const u64 c_invT   = bcast(INV_TS);
    const u64 c_negM   = bcast(-MARGIN);
    const u64 c_negL2E = bcast(-1.4426950408889634f);
    const u64 c_magic  = bcast(12582912.0f);
    const u64 c_nmagic = bcast(-12582912.0f);
    const u64 c_neg1   = bcast(-1.0f);
    const u64 c_neg2   = bcast(-2.0f);
    const u64 c_two    = bcast(2.0f);
    const u64 c_e4     = bcast(9.6181291918e-3f);
    const u64 c_e3     = bcast(5.5504108664e-2f);
    const u64 c_e2     = bcast(2.4022650696e-1f);
    const u64 c_e1     = bcast(6.9314718056e-1f);
    const u64 c_one    = bcast(1.0f);
    const u64 c_16     = bcast(0.16666667f);
    const u64 c_56     = bcast(0.83333333f);
    const u64 c_q3     = bcast(0.28571429f);
    const u64 c_q2     = bcast(0.4f);
    const u64 c_q1     = bcast(0.66666667f);

    u64 eL = 0ull, eS = 0ull;
    int accA[64], accB[64];
    #pragma unroll
    for (int i = 0; i < 64; i++) accB[i] = 0;

    // ---- prologue: resident B (1 group), then A chunks 0,1 of first tile ----
    #pragma unroll
    for (int c = 0; c < NCH; ++c)
        #pragma unroll
        for (int i = 0; i < 4; ++i)
            cp_async16(sB + (uint32_t)c * A_STAGE + soff[i], gB + gofs[i] + c * 128u);
    CP_COMMIT();
    #pragma unroll
    for (int i = 0; i < 4; ++i) cp_async16(sA + soff[i], gAc + gofs[i]);
    CP_COMMIT();
    #pragma unroll
    for (int i = 0; i < 4; ++i) cp_async16(sA + A_STAGE + soff[i], gAc + gofs[i] + 128u);
    CP_COMMIT();

    // ---- 8 tiles, banks alternating; epilogue of previous tile rides in the mainloop ----
    #pragma unroll 1
    for (int it = 0; it < 4; ++it) {
        DO_TILE(accA, accB);
        if (it == 0) { eL = 0ull; eS = 0ull; }   // discard epi of the zero bank
        DO_TILE(accB, accA);
    }
    CP_WAIT(0);

    // ---- final epilogue: last bank (accB) ----
    #pragma unroll
    for (int p = 0; p < 32; ++p) EPI_PAIR(accB[2 * p], accB[2 * p + 1]);

    // ---- reduce: one atomicAdd per CTA ----
    uint32_t slo, shi, llo, lhi;
    unpack2(slo, shi, eS);
    unpack2(llo, lhi, eL);
    float sum = __uint_as_float(llo) + __uint_as_float(lhi);
    sum = fmaf(__uint_as_float(slo) + __uint_as_float(shi), 0.5f, sum);

    #pragma unroll
    for (int o = 16; o; o >>= 1) sum += __shfl_xor_sync(0xffffffffu, sum, o);
    if (lane == 0) s_red[wid] = sum;
    __syncthreads();
    if (tid == 0) {
        float s = 0.f;
        #pragma unroll
        for (int i = 0; i < 8; i++) s += s_red[i];
        atomicAdd(&g_sum, (double)s);
    }
}

// ===================== kernel 3: diagonal correction + finalize =====================
__global__ __launch_bounds__(256) void finalize_kernel(float* out) {
    __shared__ float s_red[8];
    int tid = threadIdx.x;
    float corr = 0.f;
    for (int i = tid; i < NTOK; i += 256) {
        float l = g_diag[i] * INV_T;
        corr += softplus_fast(-l - MARGIN) - softplus_fast(l - MARGIN);
    }
    #pragma unroll
    for (int o = 16; o; o >>= 1) corr += __shfl_xor_sync(0xffffffffu, corr, o);
    int w = tid >> 5, l = tid & 31;
    if (l == 0) s_red[w] = corr;
    __syncthreads();
    if (tid == 0) {
        float tc = 0.f;
        #pragma unroll
        for (int i = 0; i < 8; i++) tc += s_red[i];
        out[0] = (float)((g_sum + (double)tc) * (1.0 / (double)NTOK));
    }
}

// ===================== launch =====================
extern "C" void kernel_launch(void* const* d_in, const int* in_sizes, int n_in,
                              void* d_out, int out_size) {
    const float* S = (const float*)d_in[0];
    const float* T = (const float*)d_in[1];
    cudaFuncSetAttribute(gemm_loss_kernel,
                         cudaFuncAttributeMaxDynamicSharedMemorySize, SMEM_SZ);
    normalize_kernel<<<NTOK, 256>>>(S, T);
    gemm_loss_kernel<<<GRIDX, 256, SMEM_SZ>>>();
    finalize_kernel<<<1, 256>>>((float*)d_out);
}

// round 11
// speedup vs baseline: 2.4687x; 2.4687x over previous
#include <cuda_runtime.h>
#include <cuda_bf16.h>
#include <cuda_fp16.h>
#include <cstdint>

// ===================== constants =====================
#define NTOK   16384
#define DIM    512
#define INV_T  14.285714285714286f   // 1/0.07
#define MARGIN 0.1f

#define GRIDX   2048                 // CTAs; each does 8 row-tiles, fixed col-tile
#define NTILES  16384
#define B_BYTES 131072               // resident B: 8 chunks x 16KB
#define A_STAGE 16384                // one A stage (128 rows x 128B)
#define SMEM_SZ (B_BYTES + 3 * A_STAGE + 1024)

typedef unsigned long long u64;

// ===================== device globals (no cudaMalloc allowed) =====================
__device__ __nv_bfloat16 g_sn[(size_t)NTOK * DIM];
__device__ __nv_bfloat16 g_tn[(size_t)NTOK * DIM];
__device__ float g_diag[NTOK];
__device__ double g_sum;

// ===================== helpers =====================
__device__ __forceinline__ uint32_t smem_u32(const void* p) {
    uint32_t a;
    asm("{ .reg .u64 t; cvta.to.shared.u64 t, %1; cvt.u32.u64 %0, t; }" : "=r"(a) : "l"(p));
    return a;
}
__device__ __forceinline__ void cp_async16(uint32_t smem, const void* gmem) {
    asm volatile("cp.async.cg.shared.global [%0], [%1], 16;" :: "r"(smem), "l"(gmem));
}
#define CP_COMMIT() asm volatile("cp.async.commit_group;" ::: "memory")
#define CP_WAIT(n)  asm volatile("cp.async.wait_group %0;" :: "n"(n) : "memory")

__device__ __forceinline__ void ldsm4(uint32_t* r, uint32_t addr) {
    asm volatile("ldmatrix.sync.aligned.m8n8.x4.shared.b16 {%0,%1,%2,%3}, [%4];"
                 : "=r"(r[0]), "=r"(r[1]), "=r"(r[2]), "=r"(r[3]) : "r"(addr));
}
// bf16 A/B inputs NOT allowed with f16 accum -> use fp16 inputs too (normalize emits fp16).
// m16n8k16 f16*f16+f16: D = 2 regs (f16x2), halving accumulator registers.
__device__ __forceinline__ void mma16816h(uint32_t* c, const uint32_t* a, uint32_t b0, uint32_t b1) {
    asm volatile(
        "mma.sync.aligned.m16n8k16.row.col.f16.f16.f16.f16 "
        "{%0,%1}, {%2,%3,%4,%5}, {%6,%7}, {%0,%1};"
        : "+r"(c[0]), "+r"(c[1])
        : "r"(a[0]), "r"(a[1]), "r"(a[2]), "r"(a[3]), "r"(b0), "r"(b1));
}
#define SWZ(off) ((off) ^ (((off) >> 3) & 0x70))

// ===================== packed f32x2 helpers =====================
__device__ __forceinline__ u64 pfma(u64 a, u64 b, u64 c) {
    u64 d; asm("fma.rn.f32x2 %0, %1, %2, %3;" : "=l"(d) : "l"(a), "l"(b), "l"(c)); return d;
}
__device__ __forceinline__ u64 pmul(u64 a, u64 b) {
    u64 d; asm("mul.rn.f32x2 %0, %1, %2;" : "=l"(d) : "l"(a), "l"(b)); return d;
}
__device__ __forceinline__ u64 padd(u64 a, u64 b) {
    u64 d; asm("add.rn.f32x2 %0, %1, %2;" : "=l"(d) : "l"(a), "l"(b)); return d;
}
__device__ __forceinline__ u64 pack2(float lo, float hi) {
    u64 d; asm("mov.b64 %0, {%1, %2};" : "=l"(d) : "f"(lo), "f"(hi)); return d;
}
__device__ __forceinline__ void unpack2(uint32_t& lo, uint32_t& hi, u64 x) {
    asm("mov.b64 {%0, %1}, %2;" : "=r"(lo), "=r"(hi) : "l"(x));
}
__device__ __forceinline__ u64 bcast(float v) {
    uint32_t b = __float_as_uint(v);
    return ((u64)b << 32) | b;
}

// ===================== scalar softplus (accurate; finalize only) =====================
__device__ __forceinline__ float softplus_fast(float x) {
    float ax = fminf(fabsf(x), 20.0f);
    float r  = fmaxf(x, 0.0f);
    float t  = ax * -1.4426950408889634f;
    float kf = t + 12582912.0f;
    int   sc = __float_as_int(kf) << 23;
    float f  = t - (kf - 12582912.0f);
    float p  = 1.3333558146e-3f;
    p = fmaf(p, f, 9.6181291918e-3f);
    p = fmaf(p, f, 5.5504108664e-2f);
    p = fmaf(p, f, 2.4022650696e-1f);
    p = fmaf(p, f, 6.9314718056e-1f);
    p = fmaf(p, f, 1.0f);
    float e = __int_as_float(__float_as_int(p) + sc);
    float d = e + 2.0f;
    float y = fmaf(d, -0.16666667f, 0.83333333f);
    y = y * fmaf(-d, y, 2.0f);
    y = y * fmaf(-d, y, 2.0f);
    float z  = e * y;
    float z2 = z * z;
    float q  = 0.22222222f;
    q = fmaf(q, z2, 0.28571429f);
    q = fmaf(q, z2, 0.4f);
    q = fmaf(q, z2, 0.66666667f);
    q = fmaf(q, z2, 2.0f);
    return fmaf(z, q, r);
}

// ===================== kernel 1: L2-normalize rows + diag dot, fp32 -> fp16 ============
__global__ __launch_bounds__(256) void normalize_kernel(const float* __restrict__ S,
                                                        const float* __restrict__ T) {
    int row = blockIdx.x;
    int tid = threadIdx.x;
    if (row == 0 && tid == 0) g_sum = 0.0;

    const float2* s2 = (const float2*)(S + (size_t)row * DIM);
    const float2* t2 = (const float2*)(T + (size_t)row * DIM);
    float2 sv = s2[tid];
    float2 tv = t2[tid];
    float a = fmaf(sv.x, sv.x, sv.y * sv.y);
    float b = fmaf(tv.x, tv.x, tv.y * tv.y);
    float c = fmaf(sv.x, tv.x, sv.y * tv.y);
    #pragma unroll
    for (int o = 16; o; o >>= 1) {
        a += __shfl_xor_sync(0xffffffffu, a, o);
        b += __shfl_xor_sync(0xffffffffu, b, o);
        c += __shfl_xor_sync(0xffffffffu, c, o);
    }
    __shared__ float sa[8], sb[8], sc[8];
    int w = tid >> 5, l = tid & 31;
    if (l == 0) { sa[w] = a; sb[w] = b; sc[w] = c; }
    __syncthreads();
    float ta = 0.f, tb = 0.f, tc = 0.f;
    #pragma unroll
    for (int i = 0; i < 8; i++) { ta += sa[i]; tb += sb[i]; tc += sc[i]; }
    float ia = rsqrtf(ta);
    float ib = rsqrtf(tb);
    if (tid == 0) g_diag[row] = tc * ia * ib;
    // fp16 storage (unit-norm components, |x| <= ~0.3: well inside fp16 range/precision)
    __half2 so = __float22half2_rn(make_float2(sv.x * ia, sv.y * ia));
    __half2 to = __float22half2_rn(make_float2(tv.x * ib, tv.y * ib));
    ((__half2*)g_sn)[(size_t)row * (DIM / 2) + tid] = so;
    ((__half2*)g_tn)[(size_t)row * (DIM / 2) + tid] = to;
}

// ===================== packed softplus pair, accumulated into eL/eS =====================
// reciprocal: chord seed (5/6 - d/6) + TWO Newton steps — R5/R9-validated (~3e-6 max err).
#define EPI_PAIR(F0, F1) do { \
    u64 _pa = pack2(F0, F1); \
    u64 _x  = pfma(_pa, c_invT, c_negM); \
    u64 _ax = _x & 0x7FFFFFFF7FFFFFFFull; \
    u64 _t  = pmul(_ax, c_negL2E); \
    u64 _kf = padd(_t, c_magic); \
    u64 _f  = pfma(padd(_kf, c_nmagic), c_neg1, _t); \
    u64 _p  = pfma(c_e4, _f, c_e3); \
    _p = pfma(_p, _f, c_e2); \
    _p = pfma(_p, _f, c_e1); \
    _p = pfma(_p, _f, c_one); \
    uint32_t _klo, _khi, _plo, _phi; \
    unpack2(_klo, _khi, _kf); \
    unpack2(_plo, _phi, _p); \
    _plo += _klo << 23; \
    _phi += _khi << 23; \
    u64 _e; asm("mov.b64 %0, {%1, %2};" : "=l"(_e) : "r"(_plo), "r"(_phi)); \
    u64 _nd = pfma(_e, c_neg1, c_neg2); \
    u64 _y  = pfma(_nd, c_16, c_56); \
    _y = pmul(_y, pfma(_nd, _y, c_two)); \
    _y = pmul(_y, pfma(_nd, _y, c_two)); \
    u64 _z  = pmul(_e, _y); \
    u64 _z2 = pmul(_z, _z); \
    u64 _q  = pfma(c_q3, _z2, c_q2); \
    _q = pfma(_q, _z2, c_q1); \
    _q = pfma(_q, _z2, c_two); \
    eL = pfma(_z, _q, eL); \
    eS = padd(eS, _x); \
    eS = padd(eS, _ax); \
} while (0)

// epilogue of one f16x2 accumulator register (2 logits)
#define EPI_PAIR_H(R32) do { \
    float2 _fv = __half22float2(*(__half2*)&(R32)); \
    EPI_PAIR(_fv.x, _fv.y); \
} while (0)

// mainloop over one 128x128 tile into ACC (f16x2), epilogue of PREV interleaved per k-step.
// 3-stage A pipeline, ONE barrier per chunk.
#define DO_TILE(ACC, PREV) do { \
    _Pragma("unroll") \
    for (int _i = 0; _i < 32; ++_i) ACC[_i] = 0u; \
    _Pragma("unroll") \
    for (int c = 0; c < 8; ++c) { \
        CP_WAIT(1); \
        __syncthreads(); \
        uint32_t aBase = sA + (uint32_t)stg * A_STAGE; \
        uint32_t bBase = sB + (uint32_t)c * A_STAGE; \
        _Pragma("unroll") \
        for (int ks = 0; ks < 4; ++ks) { \
            uint32_t afr[2][4]; \
            _Pragma("unroll") \
            for (int mi = 0; mi < 2; ++mi) { \
                int row = aRow + (mi << 4); \
                uint32_t kb = (uint32_t)(aKsel + (ks << 5)); \
                ldsm4(afr[mi], aBase + (row << 7) + (kb ^ ((row & 7) << 4))); \
            } \
            _Pragma("unroll") \
            for (int nb = 0; nb < 4; ++nb) { \
                uint32_t bfr[4]; \
                int row = bRow + (nb << 4); \
                uint32_t kb = (uint32_t)(bKsel + (ks << 5)); \
                ldsm4(bfr, bBase + (row << 7) + (kb ^ ((row & 7) << 4))); \
                _Pragma("unroll") \
                for (int mi = 0; mi < 2; ++mi) { \
                    mma16816h(&ACC[((mi << 3) + (nb << 1)) << 1],     afr[mi], bfr[0], bfr[1]); \
                    mma16816h(&ACC[((mi << 3) + (nb << 1) + 1) << 1], afr[mi], bfr[2], bfr[3]); \
                } \
            } \
            EPI_PAIR_H(PREV[(c << 2) + ks]); \
        } \
        { \
            const uint8_t* psrc = (c < 6) ? gAc : gAn; \
            uint32_t pch = (c < 6) ? (uint32_t)(c + 2) : (uint32_t)(c - 6); \
            int _s2 = stg + 2; if (_s2 >= 3) _s2 -= 3; \
            uint32_t pst = sA + (uint32_t)_s2 * A_STAGE; \
            _Pragma("unroll") \
            for (int _i = 0; _i < 4; ++_i) cp_async16(pst + soff[_i], psrc + gofs[_i] + pch * 128u); \
            CP_COMMIT(); \
        } \
        if (++stg == 3) stg = 0; \
    } \
    gAc = gAn; \
    t += GRIDX; \
    { int tnn = t + GRIDX; if (tnn >= NTILES) tnn = t; \
      gAn = (const uint8_t*)g_sn + ((size_t)(((tnn >> 10) << 3) + rband) << 17); } \
} while (0)

// ===================== kernel 2: persistent-col fp16 GEMM + pipelined softplus epilogue =====
// 256 threads (8 warps, 4x2), warp tile 32x64. B col-tile resident (128KB), A streams (3 stages).
__global__ __launch_bounds__(256, 1) void gemm_loss_kernel() {
    extern __shared__ uint8_t dynsmem[];
    __shared__ float s_red[8];

    int tid  = threadIdx.x;
    int wid  = tid >> 5;
    int lane = tid & 31;
    int bid  = blockIdx.x;

    uint32_t rbase = smem_u32(dynsmem);
    uint32_t base  = (rbase + 1023u) & ~1023u;
    uint32_t sB = base;                  // 8 resident B chunks
    uint32_t sA = base + B_BYTES;        // 3 A stages

    // this CTA: fixed col-tile bc, row-tiles t = bid + k*GRIDX (8-row bands for L2)
    int rband = bid & 7;
    int bc    = (bid & 1023) >> 3;
    int t     = bid;
    const uint8_t* gAc = (const uint8_t*)g_sn + ((size_t)(((t >> 10) << 3) + rband) << 17);
    const uint8_t* gAn = (const uint8_t*)g_sn + ((size_t)((((t + GRIDX) >> 10) << 3) + rband) << 17);
    const uint8_t* gB  = (const uint8_t*)g_tn + ((size_t)bc << 17);

    // per-thread cp.async slots: 4 x 16B covers one 16KB chunk with 256 threads
    uint32_t soff[4], gofs[4];
    #pragma unroll
    for (int i = 0; i < 4; i++) {
        int idx = tid + (i << 8);
        int r   = idx >> 3, sg = idx & 7;
        soff[i] = SWZ((r << 7) + (sg << 4));
        gofs[i] = r * (DIM * 2) + (sg << 4);
    }

    // ldmatrix components (validated R4/R9 mapping; identical for fp16)
    int wm = wid & 3, wn = wid >> 2;
    int aRow  = (wm << 5) + (lane & 15);
    int aKsel = (lane >> 4) << 4;
    int bRow  = (wn << 6) + (lane & 7) + ((lane & 16) >> 1);
    int bKsel = (lane & 8) << 1;

    // epilogue constants
    const u64 c_invT   = bcast(INV_T);
    const u64 c_negM   = bcast(-MARGIN);
    const u64 c_negL2E = bcast(-1.4426950408889634f);
    const u64 c_magic  = bcast(12582912.0f);
    const u64 c_nmagic = bcast(-12582912.0f);
    const u64 c_neg1   = bcast(-1.0f);
    const u64 c_neg2   = bcast(-2.0f);
    const u64 c_two    = bcast(2.0f);
    const u64 c_e4     = bcast(9.6181291918e-3f);
    const u64 c_e3     = bcast(5.5504108664e-2f);
    const u64 c_e2     = bcast(2.4022650696e-1f);
    const u64 c_e1     = bcast(6.9314718056e-1f);
    const u64 c_one    = bcast(1.0f);
    const u64 c_16     = bcast(0.16666667f);   // chord seed: y = 5/6 - d/6
    const u64 c_56     = bcast(0.83333333f);
    const u64 c_q3     = bcast(0.28571429f);
    const u64 c_q2     = bcast(0.4f);
    const u64 c_q1     = bcast(0.66666667f);

    u64 eL = 0ull, eS = 0ull;
    uint32_t accA[32], accB[32];       // f16x2 accumulator banks
    #pragma unroll
    for (int i = 0; i < 32; i++) accB[i] = 0u;
    int stg = 0;                        // A-stage ring counter

    // ---- prologue: resident B (1 group), then A chunks 0,1 into stages 0,1 ----
    #pragma unroll
    for (int c = 0; c < 8; ++c)
        #pragma unroll
        for (int i = 0; i < 4; ++i)
            cp_async16(sB + (uint32_t)c * A_STAGE + soff[i], gB + gofs[i] + c * 128u);
    CP_COMMIT();
    #pragma unroll
    for (int i = 0; i < 4; ++i) cp_async16(sA + soff[i], gAc + gofs[i]);
    CP_COMMIT();
    #pragma unroll
    for (int i = 0; i < 4; ++i) cp_async16(sA + A_STAGE + soff[i], gAc + gofs[i] + 128u);
    CP_COMMIT();

    // ---- 8 tiles, banks alternating; epilogue of previous tile rides in the mainloop ----
    #pragma unroll 1
    for (int it = 0; it < 4; ++it) {
        DO_TILE(accA, accB);
        if (it == 0) { eL = 0ull; eS = 0ull; }   // discard epi of the zero bank
        DO_TILE(accB, accA);
    }
    CP_WAIT(0);

    // ---- final epilogue: last bank (accB) ----
    #pragma unroll
    for (int p = 0; p < 32; ++p) EPI_PAIR_H(accB[p]);

    // ---- reduce: one atomicAdd per CTA ----
    uint32_t slo, shi, llo, lhi;
    unpack2(slo, shi, eS);
    unpack2(llo, lhi, eL);
    float sum = __uint_as_float(llo) + __uint_as_float(lhi);
    sum = fmaf(__uint_as_float(slo) + __uint_as_float(shi), 0.5f, sum);

    #pragma unroll
    for (int o = 16; o; o >>= 1) sum += __shfl_xor_sync(0xffffffffu, sum, o);
    if (lane == 0) s_red[wid] = sum;
    __syncthreads();
    if (tid == 0) {
        float s = 0.f;
        #pragma unroll
        for (int i = 0; i < 8; i++) s += s_red[i];
        atomicAdd(&g_sum, (double)s);
    }
}

// ===================== kernel 3: diagonal correction + finalize =====================
__global__ __launch_bounds__(256) void finalize_kernel(float* out) {
    __shared__ float s_red[8];
    int tid = threadIdx.x;
    float corr = 0.f;
    for (int i = tid; i < NTOK; i += 256) {
        float l = g_diag[i] * INV_T;
        corr += softplus_fast(-l - MARGIN) - softplus_fast(l - MARGIN);
    }
    #pragma unroll
    for (int o = 16; o; o >>= 1) corr += __shfl_xor_sync(0xffffffffu, corr, o);
    int w = tid >> 5, l = tid & 31;
    if (l == 0) s_red[w] = corr;
    __syncthreads();
    if (tid == 0) {
        float tc = 0.f;
        #pragma unroll
        for (int i = 0; i < 8; i++) tc += s_red[i];
        out[0] = (float)((g_sum + (double)tc) * (1.0 / (double)NTOK));
    }
}

// ===================== launch =====================
extern "C" void kernel_launch(void* const* d_in, const int* in_sizes, int n_in,
                              void* d_out, int out_size) {
    const float* S = (const float*)d_in[0];
    const float* T = (const float*)d_in[1];
    cudaFuncSetAttribute(gemm_loss_kernel,
                         cudaFuncAttributeMaxDynamicSharedMemorySize, SMEM_SZ);
    normalize_kernel<<<NTOK, 256>>>(S, T);
    gemm_loss_kernel<<<GRIDX, 256, SMEM_SZ>>>();
    finalize_kernel<<<1, 256>>>((float*)d_out);
}

// round 12
// speedup vs baseline: 2.6365x; 1.0680x over previous
#include <cuda_runtime.h>
#include <cuda_bf16.h>
#include <cuda_fp16.h>
#include <cstdint>

// ===================== constants =====================
#define NTOK   16384
#define DIM    512
#define INV_T  14.285714285714286f   // 1/0.07
#define MARGIN 0.1f

#define GRIDX   2048                 // CTAs; each: fixed 64-wide col-tile, 16 row-tiles
#define NROWT   16                   // row-tiles per CTA
#define B_CHUNK 8192                 // 64 rows x 128B
#define B_BYTES (8 * B_CHUNK)        // resident B: 64KB
#define A_STAGE 16384                // one A stage (128 rows x 128B)
#define SMEM_SZ (B_BYTES + 2 * A_STAGE + 1024)

typedef unsigned long long u64;

// ===================== device globals (no cudaMalloc allowed) =====================
__device__ __nv_bfloat16 g_sn[(size_t)NTOK * DIM];   // fp16 stored via bf16-sized array
__device__ __nv_bfloat16 g_tn[(size_t)NTOK * DIM];
__device__ float g_diag[NTOK];
__device__ double g_sum;

// ===================== helpers =====================
__device__ __forceinline__ uint32_t smem_u32(const void* p) {
    uint32_t a;
    asm("{ .reg .u64 t; cvta.to.shared.u64 t, %1; cvt.u32.u64 %0, t; }" : "=r"(a) : "l"(p));
    return a;
}
__device__ __forceinline__ void cp_async16(uint32_t smem, const void* gmem) {
    asm volatile("cp.async.cg.shared.global [%0], [%1], 16;" :: "r"(smem), "l"(gmem));
}
#define CP_COMMIT() asm volatile("cp.async.commit_group;" ::: "memory")
#define CP_WAIT(n)  asm volatile("cp.async.wait_group %0;" :: "n"(n) : "memory")

__device__ __forceinline__ void ldsm4(uint32_t* r, uint32_t addr) {
    asm volatile("ldmatrix.sync.aligned.m8n8.x4.shared.b16 {%0,%1,%2,%3}, [%4];"
                 : "=r"(r[0]), "=r"(r[1]), "=r"(r[2]), "=r"(r[3]) : "r"(addr));
}
// fp16 in / fp16 accum (R11-validated): D = 2 regs
__device__ __forceinline__ void mma16816h(uint32_t* c, const uint32_t* a, uint32_t b0, uint32_t b1) {
    asm volatile(
        "mma.sync.aligned.m16n8k16.row.col.f16.f16.f16.f16 "
        "{%0,%1}, {%2,%3,%4,%5}, {%6,%7}, {%0,%1};"
        : "+r"(c[0]), "+r"(c[1])
        : "r"(a[0]), "r"(a[1]), "r"(a[2]), "r"(a[3]), "r"(b0), "r"(b1));
}
#define SWZ(off) ((off) ^ (((off) >> 3) & 0x70))

// ===================== packed f32x2 helpers =====================
__device__ __forceinline__ u64 pfma(u64 a, u64 b, u64 c) {
    u64 d; asm("fma.rn.f32x2 %0, %1, %2, %3;" : "=l"(d) : "l"(a), "l"(b), "l"(c)); return d;
}
__device__ __forceinline__ u64 pmul(u64 a, u64 b) {
    u64 d; asm("mul.rn.f32x2 %0, %1, %2;" : "=l"(d) : "l"(a), "l"(b)); return d;
}
__device__ __forceinline__ u64 padd(u64 a, u64 b) {
    u64 d; asm("add.rn.f32x2 %0, %1, %2;" : "=l"(d) : "l"(a), "l"(b)); return d;
}
__device__ __forceinline__ u64 pack2(float lo, float hi) {
    u64 d; asm("mov.b64 %0, {%1, %2};" : "=l"(d) : "f"(lo), "f"(hi)); return d;
}
__device__ __forceinline__ void unpack2(uint32_t& lo, uint32_t& hi, u64 x) {
    asm("mov.b64 {%0, %1}, %2;" : "=r"(lo), "=r"(hi) : "l"(x));
}
__device__ __forceinline__ u64 bcast(float v) {
    uint32_t b = __float_as_uint(v);
    return ((u64)b << 32) | b;
}

// ===================== scalar softplus (accurate; finalize only) =====================
__device__ __forceinline__ float softplus_fast(float x) {
    float ax = fminf(fabsf(x), 20.0f);
    float r  = fmaxf(x, 0.0f);
    float t  = ax * -1.4426950408889634f;
    float kf = t + 12582912.0f;
    int   sc = __float_as_int(kf) << 23;
    float f  = t - (kf - 12582912.0f);
    float p  = 1.3333558146e-3f;
    p = fmaf(p, f, 9.6181291918e-3f);
    p = fmaf(p, f, 5.5504108664e-2f);
    p = fmaf(p, f, 2.4022650696e-1f);
    p = fmaf(p, f, 6.9314718056e-1f);
    p = fmaf(p, f, 1.0f);
    float e = __int_as_float(__float_as_int(p) + sc);
    float d = e + 2.0f;
    float y = fmaf(d, -0.16666667f, 0.83333333f);
    y = y * fmaf(-d, y, 2.0f);
    y = y * fmaf(-d, y, 2.0f);
    float z  = e * y;
    float z2 = z * z;
    float q  = 0.22222222f;
    q = fmaf(q, z2, 0.28571429f);
    q = fmaf(q, z2, 0.4f);
    q = fmaf(q, z2, 0.66666667f);
    q = fmaf(q, z2, 2.0f);
    return fmaf(z, q, r);
}

// ===================== kernel 1: L2-normalize rows + diag dot, fp32 -> fp16 ============
__global__ __launch_bounds__(256) void normalize_kernel(const float* __restrict__ S,
                                                        const float* __restrict__ T) {
    int row = blockIdx.x;
    int tid = threadIdx.x;
    if (row == 0 && tid == 0) g_sum = 0.0;

    const float2* s2 = (const float2*)(S + (size_t)row * DIM);
    const float2* t2 = (const float2*)(T + (size_t)row * DIM);
    float2 sv = s2[tid];
    float2 tv = t2[tid];
    float a = fmaf(sv.x, sv.x, sv.y * sv.y);
    float b = fmaf(tv.x, tv.x, tv.y * tv.y);
    float c = fmaf(sv.x, tv.x, sv.y * tv.y);
    #pragma unroll
    for (int o = 16; o; o >>= 1) {
        a += __shfl_xor_sync(0xffffffffu, a, o);
        b += __shfl_xor_sync(0xffffffffu, b, o);
        c += __shfl_xor_sync(0xffffffffu, c, o);
    }
    __shared__ float sa[8], sb[8], sc[8];
    int w = tid >> 5, l = tid & 31;
    if (l == 0) { sa[w] = a; sb[w] = b; sc[w] = c; }
    __syncthreads();
    float ta = 0.f, tb = 0.f, tc = 0.f;
    #pragma unroll
    for (int i = 0; i < 8; i++) { ta += sa[i]; tb += sb[i]; tc += sc[i]; }
    float ia = rsqrtf(ta);
    float ib = rsqrtf(tb);
    if (tid == 0) g_diag[row] = tc * ia * ib;
    __half2 so = __float22half2_rn(make_float2(sv.x * ia, sv.y * ia));
    __half2 to = __float22half2_rn(make_float2(tv.x * ib, tv.y * ib));
    ((__half2*)g_sn)[(size_t)row * (DIM / 2) + tid] = so;
    ((__half2*)g_tn)[(size_t)row * (DIM / 2) + tid] = to;
}

// ===================== packed softplus pair, accumulated into eL/eS =====================
#define EPI_PAIR(F0, F1) do { \
    u64 _pa = pack2(F0, F1); \
    u64 _x  = pfma(_pa, c_invT, c_negM); \
    u64 _ax = _x & 0x7FFFFFFF7FFFFFFFull; \
    u64 _t  = pmul(_ax, c_negL2E); \
    u64 _kf = padd(_t, c_magic); \
    u64 _f  = pfma(padd(_kf, c_nmagic), c_neg1, _t); \
    u64 _p  = pfma(c_e4, _f, c_e3); \
    _p = pfma(_p, _f, c_e2); \
    _p = pfma(_p, _f, c_e1); \
    _p = pfma(_p, _f, c_one); \
    uint32_t _klo, _khi, _plo, _phi; \
    unpack2(_klo, _khi, _kf); \
    unpack2(_plo, _phi, _p); \
    _plo += _klo << 23; \
    _phi += _khi << 23; \
    u64 _e; asm("mov.b64 %0, {%1, %2};" : "=l"(_e) : "r"(_plo), "r"(_phi)); \
    u64 _nd = pfma(_e, c_neg1, c_neg2); \
    u64 _y  = pfma(_nd, c_16, c_56); \
    _y = pmul(_y, pfma(_nd, _y, c_two)); \
    _y = pmul(_y, pfma(_nd, _y, c_two)); \
    u64 _z  = pmul(_e, _y); \
    u64 _z2 = pmul(_z, _z); \
    u64 _q  = pfma(c_q3, _z2, c_q2); \
    _q = pfma(_q, _z2, c_q1); \
    _q = pfma(_q, _z2, c_two); \
    eL = pfma(_z, _q, eL); \
    eS = padd(eS, _x); \
    eS = padd(eS, _ax); \
} while (0)

#define EPI_PAIR_H(R32) do { \
    float2 _fv = __half22float2(*(__half2*)&(R32)); \
    EPI_PAIR(_fv.x, _fv.y); \
} while (0)

// mainloop over one 128x64 tile into ACC (16 f16x2), epilogue of PREV (1 pair / 2 ks)
#define DO_TILE(ACC, PREV) do { \
    _Pragma("unroll") \
    for (int _i = 0; _i < 16; ++_i) ACC[_i] = 0u; \
    _Pragma("unroll") \
    for (int c = 0; c < 8; ++c) { \
        CP_WAIT(1); \
        __syncthreads(); \
        uint32_t aBase = sA + (uint32_t)(tcount & 1) * 0 + (uint32_t)(c & 1) * A_STAGE; \
        uint32_t bBase = sB + (uint32_t)c * B_CHUNK; \
        _Pragma("unroll") \
        for (int ks = 0; ks < 4; ++ks) { \
            uint32_t afr[2][4]; \
            _Pragma("unroll") \
            for (int mi = 0; mi < 2; ++mi) { \
                int row = aRow + (mi << 4); \
                uint32_t kb = (uint32_t)(aKsel + (ks << 5)); \
                ldsm4(afr[mi], aBase + (row << 7) + (kb ^ ((row & 7) << 4))); \
            } \
            _Pragma("unroll") \
            for (int nb = 0; nb < 2; ++nb) { \
                uint32_t bfr[4]; \
                int row = bRow + (nb << 4); \
                uint32_t kb = (uint32_t)(bKsel + (ks << 5)); \
                ldsm4(bfr, bBase + (row << 7) + (kb ^ ((row & 7) << 4))); \
                _Pragma("unroll") \
                for (int mi = 0; mi < 2; ++mi) { \
                    mma16816h(&ACC[((mi << 2) + (nb << 1)) << 1],     afr[mi], bfr[0], bfr[1]); \
                    mma16816h(&ACC[((mi << 2) + (nb << 1) + 1) << 1], afr[mi], bfr[2], bfr[3]); \
                } \
            } \
            if ((ks & 1) == 0) EPI_PAIR_H(PREV[(c << 1) + (ks >> 1)]); \
        } \
        __syncthreads(); \
        { \
            const uint8_t* psrc = (c < 6) ? gAc : gAn; \
            uint32_t pch = (c < 6) ? (uint32_t)(c + 2) : (uint32_t)(c - 6); \
            uint32_t pst = sA + (uint32_t)(c & 1) * A_STAGE; \
            _Pragma("unroll") \
            for (int _i = 0; _i < 4; ++_i) cp_async16(pst + soff[_i], psrc + gofs[_i] + pch * 128u); \
            CP_COMMIT(); \
        } \
    } \
    gAc = gAn; \
    tcount++; \
    { int tn = (tcount + 1 < NROWT) ? (tcount + 1) : tcount; \
      gAn = (const uint8_t*)g_sn + ((size_t)((tn << 3) + rband) << 17); } \
} while (0)

// ===================== kernel 2: 2-CTA/SM fp16 GEMM (128x64 tiles) + pipelined epilogue =====
// 256 threads (8 warps, 4x2), warp tile 32x32. B col-tile (64 cols) resident: 64KB.
__global__ __launch_bounds__(256, 2) void gemm_loss_kernel() {
    extern __shared__ uint8_t dynsmem[];
    __shared__ float s_red[8];

    int tid  = threadIdx.x;
    int wid  = tid >> 5;
    int lane = tid & 31;
    int bid  = blockIdx.x;

    uint32_t rbase = smem_u32(dynsmem);
    uint32_t base  = (rbase + 1023u) & ~1023u;
    uint32_t sB = base;                  // 8 resident B chunks (64 rows each)
    uint32_t sA = base + B_BYTES;        // 2 A stages

    // this CTA: fixed 64-wide col-tile bc (0..255), row-tiles (it<<3)+rband
    int rband = bid & 7;
    int bc    = bid >> 3;
    int tcount = 0;
    const uint8_t* gAc = (const uint8_t*)g_sn + ((size_t)rband << 17);
    const uint8_t* gAn = (const uint8_t*)g_sn + ((size_t)(8 + rband) << 17);
    const uint8_t* gB  = (const uint8_t*)g_tn + ((size_t)bc << 16);   // 64 rows * 1024B

    // A cp.async slots: 16KB chunk / 256 threads = 4 x 16B
    uint32_t soff[4], gofs[4];
    #pragma unroll
    for (int i = 0; i < 4; i++) {
        int idx = tid + (i << 8);
        int r   = idx >> 3, sg = idx & 7;
        soff[i] = SWZ((r << 7) + (sg << 4));
        gofs[i] = r * (DIM * 2) + (sg << 4);
    }
    // B cp.async slots: 8KB chunk / 256 threads = 2 x 16B
    uint32_t soffB[2], gofsB[2];
    #pragma unroll
    for (int i = 0; i < 2; i++) {
        int idx = tid + (i << 8);        // 0..511
        int r   = idx >> 3, sg = idx & 7;    // r 0..63
        soffB[i] = SWZ((r << 7) + (sg << 4));
        gofsB[i] = r * (DIM * 2) + (sg << 4);
    }

    // warp grid 4(M) x 2(N); warp tile 32x32
    int wm = wid & 3, wn = wid >> 2;
    int aRow  = (wm << 5) + (lane & 15);
    int aKsel = (lane >> 4) << 4;
    int bRow  = (wn << 5) + (lane & 7) + ((lane & 16) >> 1);
    int bKsel = (lane & 8) << 1;

    // epilogue constants
    const u64 c_invT   = bcast(INV_T);
    const u64 c_negM   = bcast(-MARGIN);
    const u64 c_negL2E = bcast(-1.4426950408889634f);
    const u64 c_magic  = bcast(12582912.0f);
    const u64 c_nmagic = bcast(-12582912.0f);
    const u64 c_neg1   = bcast(-1.0f);
    const u64 c_neg2   = bcast(-2.0f);
    const u64 c_two    = bcast(2.0f);
    const u64 c_e4     = bcast(9.6181291918e-3f);
    const u64 c_e3     = bcast(5.5504108664e-2f);
    const u64 c_e2     = bcast(2.4022650696e-1f);
    const u64 c_e1     = bcast(6.9314718056e-1f);
    const u64 c_one    = bcast(1.0f);
    const u64 c_16     = bcast(0.16666667f);
    const u64 c_56     = bcast(0.83333333f);
    const u64 c_q3     = bcast(0.28571429f);
    const u64 c_q2     = bcast(0.4f);
    const u64 c_q1     = bcast(0.66666667f);

    u64 eL = 0ull, eS = 0ull;
    uint32_t accA[16], accB[16];
    #pragma unroll
    for (int i = 0; i < 16; i++) accB[i] = 0u;

    // ---- prologue: resident B (1 group), then A chunks 0,1 of first tile ----
    #pragma unroll
    for (int c = 0; c < 8; ++c)
        #pragma unroll
        for (int i = 0; i < 2; ++i)
            cp_async16(sB + (uint32_t)c * B_CHUNK + soffB[i], gB + gofsB[i] + c * 128u);
    CP_COMMIT();
    #pragma unroll
    for (int i = 0; i < 4; ++i) cp_async16(sA + soff[i], gAc + gofs[i]);
    CP_COMMIT();
    #pragma unroll
    for (int i = 0; i < 4; ++i) cp_async16(sA + A_STAGE + soff[i], gAc + gofs[i] + 128u);
    CP_COMMIT();

    // ---- 16 tiles, banks alternating; epilogue of previous tile rides in mainloop ----
    #pragma unroll 1
    for (int it = 0; it < NROWT / 2; ++it) {
        DO_TILE(accA, accB);
        if (it == 0) { eL = 0ull; eS = 0ull; }   // discard epi of the zero bank
        DO_TILE(accB, accA);
    }
    CP_WAIT(0);

    // ---- final epilogue: last bank ----
    #pragma unroll
    for (int p = 0; p < 16; ++p) EPI_PAIR_H(accB[p]);

    // ---- reduce: one atomicAdd per CTA ----
    uint32_t slo, shi, llo, lhi;
    unpack2(slo, shi, eS);
    unpack2(llo, lhi, eL);
    float sum = __uint_as_float(llo) + __uint_as_float(lhi);
    sum = fmaf(__uint_as_float(slo) + __uint_as_float(shi), 0.5f, sum);

    #pragma unroll
    for (int o = 16; o; o >>= 1) sum += __shfl_xor_sync(0xffffffffu, sum, o);
    if (lane == 0) s_red[wid] = sum;
    __syncthreads();
    if (tid == 0) {
        float s = 0.f;
        #pragma unroll
        for (int i = 0; i < 8; i++) s += s_red[i];
        atomicAdd(&g_sum, (double)s);
    }
}

// ===================== kernel 3: diagonal correction + finalize =====================
__global__ __launch_bounds__(256) void finalize_kernel(float* out) {
    __shared__ float s_red[8];
    int tid = threadIdx.x;
    float corr = 0.f;
    for (int i = tid; i < NTOK; i += 256) {
        float l = g_diag[i] * INV_T;
        corr += softplus_fast(-l - MARGIN) - softplus_fast(l - MARGIN);
    }
    #pragma unroll
    for (int o = 16; o; o >>= 1) corr += __shfl_xor_sync(0xffffffffu, corr, o);
    int w = tid >> 5, l = tid & 31;
    if (l == 0) s_red[w] = corr;
    __syncthreads();
    if (tid == 0) {
        float tc = 0.f;
        #pragma unroll
        for (int i = 0; i < 8; i++) tc += s_red[i];
        out[0] = (float)((g_sum + (double)tc) * (1.0 / (double)NTOK));
    }
}

// ===================== launch =====================
extern "C" void kernel_launch(void* const* d_in, const int* in_sizes, int n_in,
                              void* d_out, int out_size) {
    const float* S = (const float*)d_in[0];
    const float* T = (const float*)d_in[1];
    cudaFuncSetAttribute(gemm_loss_kernel,
                         cudaFuncAttributeMaxDynamicSharedMemorySize, SMEM_SZ);
    normalize_kernel<<<NTOK, 256>>>(S, T);
    gemm_loss_kernel<<<GRIDX, 256, SMEM_SZ>>>();
    finalize_kernel<<<1, 256>>>((float*)d_out);
}